// round 1
// baseline (speedup 1.0000x reference)
#include <cuda_runtime.h>
#include <cuda_bf16.h>
#include <math.h>

// ---------------- problem constants ----------------
#define BB   2
#define LL   512
#define DD   256
#define PDIM 64
#define HH   8
#define PP   4
#define HDH  32          // head dim
#define HP3  96          // H*P*3
#define OUTD 896
#define NROW (BB*LL)     // 1024

#define SCALAR_SCALE 0.17677669529663687f   // 1/sqrt(32)
#define POINT_SCALE  0.2886751345948129f    // 1/sqrt(12)

// ---------------- device scratch ----------------
__device__ float g_qs[BB*HH*LL*HDH];
__device__ float g_ks[BB*HH*LL*HDH];
__device__ float g_vs[BB*HH*LL*HDH];
__device__ float g_qp[BB*HH*LL*12];
__device__ float g_kp[BB*HH*LL*12];
__device__ float g_vp[BB*HH*LL*12];
__device__ float g_qn[BB*HH*LL];
__device__ float g_kn[BB*HH*LL];
__device__ float g_osc[NROW*256];
__device__ float g_opair[NROW*512];
__device__ float g_opts[NROW*96];

// ---------------- mask dtype sniffing ----------------
__device__ __forceinline__ int mask_mode(const void* m) {
    int w0 = *(const int*)m;
    if (w0 == 0x3f800000) return 2;   // float32 ones
    if (w0 == 1)          return 1;   // int32
    return 0;                         // byte-sized bool
}
__device__ __forceinline__ bool mask_at(const void* m, int mode, int j) {
    if (mode == 2) return ((const float*)m)[j] != 0.0f;
    if (mode == 1) return ((const int*)m)[j]   != 0;
    return ((const unsigned char*)m)[j] != 0;
}

// =====================================================================
// K1: projections. 8 rows per block, 256 threads.
// Computes q_s/k_s/v_s (transposed to [b][h][l][hd]), point projections,
// global-frame transform, and point norms.
// =====================================================================
__global__ __launch_bounds__(256) void k_proj(
    const float* __restrict__ node,
    const float* __restrict__ rot,
    const float* __restrict__ trans,
    const float* __restrict__ Wq, const float* __restrict__ Wk, const float* __restrict__ Wv,
    const float* __restrict__ Wqp, const float* __restrict__ Wkp, const float* __restrict__ Wvp)
{
    __shared__ float xs[8][DD];
    __shared__ float lp[3][8][HP3];   // local points q/k/v
    __shared__ float gp[3][8][HP3];   // global points
    __shared__ float Rs[8][9];
    __shared__ float Ts[8][3];

    const int tid  = threadIdx.x;
    const int row0 = blockIdx.x * 8;

    for (int i = tid; i < 8*DD; i += 256) {
        int r = i >> 8, d = i & 255;
        xs[r][d] = node[(row0 + r)*DD + d];
    }
    if (tid < 96) {           // 8 rows x 12 = R(9)+T(3)
        int r = tid / 12, c = tid % 12;
        if (c < 9) Rs[r][c]   = rot[(row0 + r)*9 + c];
        else       Ts[r][c-9] = trans[(row0 + r)*3 + (c-9)];
    }
    __syncthreads();

    // ---- scalar projections: thread = output column ----
    {
        float aq[8], ak[8], av[8];
        #pragma unroll
        for (int r = 0; r < 8; r++) { aq[r]=0.f; ak[r]=0.f; av[r]=0.f; }
        const int c = tid;
        for (int d = 0; d < DD; d++) {
            float wq = Wq[d*DD + c], wk = Wk[d*DD + c], wv = Wv[d*DD + c];
            #pragma unroll
            for (int r = 0; r < 8; r++) {
                float x = xs[r][d];
                aq[r] += x*wq; ak[r] += x*wk; av[r] += x*wv;
            }
        }
        const int h = c >> 5, hd = c & 31;
        #pragma unroll
        for (int r = 0; r < 8; r++) {
            int n = row0 + r, b = n >> 9, l = n & 511;
            int o = ((b*HH + h)*LL + l)*HDH + hd;
            g_qs[o] = aq[r]; g_ks[o] = ak[r]; g_vs[o] = av[r];
        }
    }

    // ---- point projections: threads < 96 ----
    if (tid < 96) {
        float pq[8], pk[8], pv[8];
        #pragma unroll
        for (int r = 0; r < 8; r++) { pq[r]=0.f; pk[r]=0.f; pv[r]=0.f; }
        for (int d = 0; d < DD; d++) {
            float wq = Wqp[d*96 + tid], wk = Wkp[d*96 + tid], wv = Wvp[d*96 + tid];
            #pragma unroll
            for (int r = 0; r < 8; r++) {
                float x = xs[r][d];
                pq[r] += x*wq; pk[r] += x*wk; pv[r] += x*wv;
            }
        }
        #pragma unroll
        for (int r = 0; r < 8; r++) {
            lp[0][r][tid] = pq[r]; lp[1][r][tid] = pk[r]; lp[2][r][tid] = pv[r];
        }
    }
    __syncthreads();

    // ---- global-frame transform: g[i] = sum_j R[i][j]*p[j] + t[i] ----
    for (int i = tid; i < 3*8*96; i += 256) {
        int m = i / 768, rem = i % 768, r = rem / 96, c = rem % 96;
        int base = (c/3)*3, ax = c % 3;
        float v = Rs[r][ax*3+0]*lp[m][r][base+0]
                + Rs[r][ax*3+1]*lp[m][r][base+1]
                + Rs[r][ax*3+2]*lp[m][r][base+2] + Ts[r][ax];
        gp[m][r][c] = v;
    }
    __syncthreads();

    // ---- write global points to gmem (layout [b][h][l][12]) ----
    for (int i = tid; i < 3*8*96; i += 256) {
        int m = i / 768, rem = i % 768, r = rem / 96, c = rem % 96;
        int h = c / 12, cc = c % 12;
        int n = row0 + r, b = n >> 9, l = n & 511;
        int o = ((b*HH + h)*LL + l)*12 + cc;
        float v = gp[m][r][c];
        if (m == 0)      g_qp[o] = v;
        else if (m == 1) g_kp[o] = v;
        else             g_vp[o] = v;
    }

    // ---- point norms (q and k only): 2 * 8rows * 8heads = 128 items ----
    if (tid < 128) {
        int m = tid >> 6, r = (tid >> 3) & 7, h = tid & 7;
        float s = 0.f;
        #pragma unroll
        for (int c = 0; c < 12; c++) {
            float v = gp[m][r][h*12 + c];
            s += v*v;
        }
        int n = row0 + r, b = n >> 9, l = n & 511;
        int o = (b*HH + h)*LL + l;
        if (m == 0) g_qn[o] = s; else g_kn[o] = s;
    }
}

// =====================================================================
// K2: fused attention. One block per (b,i), 256 threads, big dyn smem.
// Stages pair[b,i,:,:] tile once; computes logits (scalar + points +
// pair bias), softmax, and attn @ {v_s, v_pg, pair}.
// =====================================================================
#define PAIR_STRIDE 65
#define K2_SMEM_FLOATS (512*PAIR_STRIDE + 4096 + 4096 + 512 + 256 + 96 + 8 + 8)
#define K2_SMEM_BYTES (K2_SMEM_FLOATS * 4)

__global__ __launch_bounds__(256) void k_attn(
    const float* __restrict__ pair,
    const void*  __restrict__ maskp,
    const float* __restrict__ Wpb_g,
    const float* __restrict__ hw)
{
    extern __shared__ float sm[];
    float* pairT = sm;                       // 512*65
    float* attn  = pairT + 512*PAIR_STRIDE;  // [h*512+j]
    float* pb    = attn + 4096;              // [j*8+h]
    float* wpb   = pb + 4096;                // 64*8
    float* qs    = wpb + 512;                // 8*32
    float* qp    = qs + 256;                 // 8*12
    float* qn    = qp + 96;                  // 8
    float* wsp   = qn + 8;                   // 8

    const int tid = threadIdx.x;
    const int i   = blockIdx.x;
    const int b   = blockIdx.y;

    for (int t = tid; t < 512; t += 256) wpb[t] = Wpb_g[t];
    {
        int h = tid >> 5, d = tid & 31;
        qs[tid] = g_qs[((b*HH + h)*LL + i)*HDH + d];
    }
    if (tid < 96) {
        int h = tid / 12, c = tid % 12;
        qp[tid] = g_qp[((b*HH + h)*LL + i)*12 + c];
    }
    if (tid < 8) {
        qn[tid]  = g_qn[(b*HH + tid)*LL + i];
        wsp[tid] = log1pf(expf(hw[tid]));    // softplus
    }
    __syncthreads();

    // ---- stream pair tile into smem, accumulate pair bias on the fly ----
    {
        const float* psrc = pair + ((size_t)(b*LL + i))*LL*PDIM;
        const float4* p4  = (const float4*)(psrc + tid*128);
        const int j0 = tid*2;
        float acc[2][8];
        #pragma unroll
        for (int jl = 0; jl < 2; jl++)
            #pragma unroll
            for (int h = 0; h < 8; h++) acc[jl][h] = 0.f;
        #pragma unroll
        for (int q = 0; q < 32; q++) {
            float4 v = p4[q];
            int off = q*4;
            int jl = off >> 6;
            int d  = off & 63;
            pairT[(j0+jl)*PAIR_STRIDE + d+0] = v.x;
            pairT[(j0+jl)*PAIR_STRIDE + d+1] = v.y;
            pairT[(j0+jl)*PAIR_STRIDE + d+2] = v.z;
            pairT[(j0+jl)*PAIR_STRIDE + d+3] = v.w;
            #pragma unroll
            for (int h = 0; h < 8; h++) {
                acc[jl][h] += v.x*wpb[(d+0)*8+h] + v.y*wpb[(d+1)*8+h]
                            + v.z*wpb[(d+2)*8+h] + v.w*wpb[(d+3)*8+h];
            }
        }
        #pragma unroll
        for (int jl = 0; jl < 2; jl++)
            #pragma unroll
            for (int h = 0; h < 8; h++) pb[(j0+jl)*8 + h] = acc[jl][h];
    }
    __syncthreads();

    // ---- logits ----
    const int mmode = mask_mode(maskp);
    for (int idx = tid; idx < 4096; idx += 256) {
        int h = idx >> 9, j = idx & 511;
        const float4* kv = (const float4*)&g_ks[((b*HH + h)*LL + j)*HDH];
        float s = 0.f;
        #pragma unroll
        for (int t4 = 0; t4 < 8; t4++) {
            float4 kk = kv[t4];
            s += qs[h*32 + t4*4+0]*kk.x + qs[h*32 + t4*4+1]*kk.y
               + qs[h*32 + t4*4+2]*kk.z + qs[h*32 + t4*4+3]*kk.w;
        }
        float qkp = 0.f;
        const float* kp = &g_kp[((b*HH + h)*LL + j)*12];
        #pragma unroll
        for (int c = 0; c < 12; c++) qkp += qp[h*12 + c]*kp[c];
        float dist  = qn[h] + g_kn[(b*HH + h)*LL + j] - 2.f*qkp;
        float logit = s*SCALAR_SCALE - 0.5f*wsp[h]*POINT_SCALE*dist + pb[j*8 + h];
        if (!mask_at(maskp, mmode, b*LL + j)) logit -= 1e9f;
        attn[h*512 + j] = logit;
    }
    __syncthreads();

    // ---- softmax: warp w handles head w ----
    {
        int w = tid >> 5, lane = tid & 31;
        float* row = attn + w*512;
        float mx = -1e30f;
        #pragma unroll
        for (int j = lane; j < 512; j += 32) mx = fmaxf(mx, row[j]);
        #pragma unroll
        for (int o = 16; o; o >>= 1) mx = fmaxf(mx, __shfl_xor_sync(0xffffffffu, mx, o));
        float sum = 0.f;
        #pragma unroll
        for (int j = lane; j < 512; j += 32) {
            float e = __expf(row[j] - mx);
            row[j] = e; sum += e;
        }
        #pragma unroll
        for (int o = 16; o; o >>= 1) sum += __shfl_xor_sync(0xffffffffu, sum, o);
        float inv = 1.f / sum;
        #pragma unroll
        for (int j = lane; j < 512; j += 32) row[j] *= inv;
    }
    __syncthreads();

    // ---- out_scalar: thread = (h,d) ----
    {
        int h = tid >> 5, d = tid & 31;
        const float* vsrc = &g_vs[(b*HH + h)*LL*HDH + d];
        const float* arow = attn + h*512;
        float acc = 0.f;
        #pragma unroll 4
        for (int j = 0; j < 512; j++) acc += arow[j]*vsrc[j*HDH];
        g_osc[(b*LL + i)*256 + tid] = acc;
    }
    // ---- out_points (global frame): threads < 96 ----
    if (tid < 96) {
        int h = tid / 12, c = tid % 12;
        const float* vsrc = &g_vp[(b*HH + h)*LL*12 + c];
        const float* arow = attn + h*512;
        float acc = 0.f;
        #pragma unroll 4
        for (int j = 0; j < 512; j++) acc += arow[j]*vsrc[j*12];
        g_opts[(b*LL + i)*96 + tid] = acc;
    }
    // ---- out_pair: thread = (h,d), two passes over h ----
    #pragma unroll
    for (int pass = 0; pass < 2; pass++) {
        int h = (tid >> 6) + pass*4;
        int d = tid & 63;
        const float* arow = attn + h*512;
        float acc = 0.f;
        #pragma unroll 4
        for (int j = 0; j < 512; j++) acc += arow[j]*pairT[j*PAIR_STRIDE + d];
        g_opair[(b*LL + i)*512 + h*64 + d] = acc;
    }
}

// =====================================================================
// K3: assemble feature vector, local-frame transform + norms,
// feat @ Wout + bout + residual, LayerNorm. 8 rows/block.
// =====================================================================
__global__ __launch_bounds__(256) void k_out(
    const float* __restrict__ node,
    const float* __restrict__ rot,
    const float* __restrict__ trans,
    const float* __restrict__ Wout,
    const float* __restrict__ bout,
    const float* __restrict__ gamma,
    const float* __restrict__ beta,
    float* __restrict__ out)
{
    __shared__ float feat[8][OUTD];
    __shared__ float xsm[8][256];
    __shared__ float Rs[8][9];
    __shared__ float Ts[8][3];
    __shared__ float s_mu[8], s_inv[8];

    const int tid  = threadIdx.x;
    const int row0 = blockIdx.x * 8;

    for (int i = tid; i < 8*256; i += 256) {
        int r = i >> 8, d = i & 255;
        feat[r][d] = g_osc[(row0 + r)*256 + d];
    }
    for (int i = tid; i < 8*512; i += 256) {
        int r = i >> 9, d = i & 511;
        feat[r][256 + d] = g_opair[(row0 + r)*512 + d];
    }
    if (tid < 96) {
        int r = tid / 12, c = tid % 12;
        if (c < 9) Rs[r][c]   = rot[(row0 + r)*9 + c];
        else       Ts[r][c-9] = trans[(row0 + r)*3 + (c-9)];
    }
    __syncthreads();

    // points: local = R^T (g - t); 8 rows * 32 (h,p) = 256 items
    {
        int r = tid >> 5, hp = tid & 31;
        const float* g = &g_opts[(row0 + r)*96 + hp*3];
        float d0 = g[0] - Ts[r][0];
        float d1 = g[1] - Ts[r][1];
        float d2 = g[2] - Ts[r][2];
        float l0 = Rs[r][0]*d0 + Rs[r][3]*d1 + Rs[r][6]*d2;
        float l1 = Rs[r][1]*d0 + Rs[r][4]*d1 + Rs[r][7]*d2;
        float l2 = Rs[r][2]*d0 + Rs[r][5]*d1 + Rs[r][8]*d2;
        feat[r][768 + hp*3 + 0] = l0;
        feat[r][768 + hp*3 + 1] = l1;
        feat[r][768 + hp*3 + 2] = l2;
        feat[r][864 + hp] = sqrtf(l0*l0 + l1*l1 + l2*l2);
    }
    __syncthreads();

    // out = feat @ Wout  (thread = output column d, 8 rows)
    float acc[8];
    #pragma unroll
    for (int r = 0; r < 8; r++) acc[r] = 0.f;
    const int d = tid;
    for (int f = 0; f < OUTD; f += 4) {
        float w0 = Wout[(f+0)*256 + d];
        float w1 = Wout[(f+1)*256 + d];
        float w2 = Wout[(f+2)*256 + d];
        float w3 = Wout[(f+3)*256 + d];
        #pragma unroll
        for (int r = 0; r < 8; r++) {
            float4 fv = *(const float4*)&feat[r][f];
            acc[r] += fv.x*w0 + fv.y*w1 + fv.z*w2 + fv.w*w3;
        }
    }

    const float bo = bout[d];
    #pragma unroll
    for (int r = 0; r < 8; r++)
        xsm[r][d] = node[(row0 + r)*256 + d] + acc[r] + bo;
    __syncthreads();

    // LayerNorm: warp w handles row w
    {
        int w = tid >> 5, lane = tid & 31;
        float s = 0.f;
        #pragma unroll
        for (int j = lane; j < 256; j += 32) s += xsm[w][j];
        #pragma unroll
        for (int o = 16; o; o >>= 1) s += __shfl_xor_sync(0xffffffffu, s, o);
        float mu = s * (1.f/256.f);
        float v = 0.f;
        #pragma unroll
        for (int j = lane; j < 256; j += 32) {
            float t = xsm[w][j] - mu;
            v += t*t;
        }
        #pragma unroll
        for (int o = 16; o; o >>= 1) v += __shfl_xor_sync(0xffffffffu, v, o);
        if (lane == 0) {
            s_mu[w]  = mu;
            s_inv[w] = rsqrtf(v*(1.f/256.f) + 1e-5f);
        }
    }
    __syncthreads();

    const float ga = gamma[d], be = beta[d];
    #pragma unroll
    for (int r = 0; r < 8; r++)
        out[(row0 + r)*256 + d] = (xsm[r][d] - s_mu[r])*s_inv[r]*ga + be;
}

// =====================================================================
extern "C" void kernel_launch(void* const* d_in, const int* in_sizes, int n_in,
                              void* d_out, int out_size)
{
    const float* node  = (const float*)d_in[0];
    const float* pair  = (const float*)d_in[1];
    const float* rot   = (const float*)d_in[2];
    const float* trans = (const float*)d_in[3];
    const void*  maskp = (const void*) d_in[4];
    const float* Wq    = (const float*)d_in[5];
    const float* Wk    = (const float*)d_in[6];
    const float* Wv    = (const float*)d_in[7];
    const float* Wqp   = (const float*)d_in[8];
    const float* Wkp   = (const float*)d_in[9];
    const float* Wvp   = (const float*)d_in[10];
    const float* Wpb   = (const float*)d_in[11];
    const float* hw    = (const float*)d_in[12];
    const float* Wout  = (const float*)d_in[13];
    const float* bout  = (const float*)d_in[14];
    const float* gamma = (const float*)d_in[15];
    const float* beta  = (const float*)d_in[16];
    float* out = (float*)d_out;

    static bool attr_done = false;
    if (!attr_done) {
        cudaFuncSetAttribute(k_attn, cudaFuncAttributeMaxDynamicSharedMemorySize,
                             K2_SMEM_BYTES);
        attr_done = true;
    }

    k_proj<<<NROW/8, 256>>>(node, rot, trans, Wq, Wk, Wv, Wqp, Wkp, Wvp);
    k_attn<<<dim3(LL, BB), 256, K2_SMEM_BYTES>>>(pair, maskp, Wpb, hw);
    k_out<<<NROW/8, 256>>>(node, rot, trans, Wout, bout, gamma, beta, out);
}

// round 5
// speedup vs baseline: 2.2867x; 2.2867x over previous
#include <cuda_runtime.h>
#include <cuda_bf16.h>
#include <math.h>

// ---------------- problem constants ----------------
#define BB   2
#define LL   512
#define DD   256
#define PDIM 64
#define HH   8
#define PP   4
#define HDH  32
#define OUTD 896
#define NROW (BB*LL)

#define SCALAR_SCALE 0.17677669529663687f   // 1/sqrt(32)
#define POINT_SCALE  0.2886751345948129f    // 1/sqrt(12)

#define IT 4     // queries per attention block
#define JT 32    // j tile
#define NJT (LL/JT)

#define KSPLIT 4
#define KCH (OUTD/KSPLIT)   // 224

// ---------------- device scratch ----------------
__device__ float g_qs[BB*HH*LL*HDH];
__device__ float g_ks[BB*HH*LL*HDH];
__device__ float g_vs[BB*HH*LL*HDH];
__device__ float g_qp[BB*HH*LL*12];
__device__ float g_kp[BB*HH*LL*12];
__device__ float g_vp[BB*HH*LL*12];
__device__ float g_qn[BB*HH*LL];
__device__ float g_kn[BB*HH*LL];
__device__ float g_feat[NROW*OUTD];
__device__ float g_part[KSPLIT*NROW*DD];

// ---------------- mask dtype sniffing ----------------
__device__ __forceinline__ int mask_mode(const void* m) {
    int w0 = *(const int*)m;
    if (w0 == 0x3f800000) return 2;
    if (w0 == 1)          return 1;
    return 0;
}
__device__ __forceinline__ bool mask_at(const void* m, int mode, int j) {
    if (mode == 2) return ((const float*)m)[j] != 0.0f;
    if (mode == 1) return ((const int*)m)[j]   != 0;
    return ((const unsigned char*)m)[j] != 0;
}

// =====================================================================
// K1: projections. 8 rows/block, blockIdx.y selects matrix group:
//   y=0/1/2 -> Wq/Wk/Wv scalar (256 cols); y=3 -> all point matrices.
// =====================================================================
__global__ __launch_bounds__(256) void k_proj(
    const float* __restrict__ node,
    const float* __restrict__ rot,
    const float* __restrict__ trans,
    const float* __restrict__ Wq, const float* __restrict__ Wk, const float* __restrict__ Wv,
    const float* __restrict__ Wqp, const float* __restrict__ Wkp, const float* __restrict__ Wvp)
{
    __shared__ float xs[8][DD];
    __shared__ float lp[3][8][96];
    __shared__ float gp[3][8][96];
    __shared__ float Rs[8][9];
    __shared__ float Ts[8][3];

    const int tid  = threadIdx.x;
    const int row0 = blockIdx.x * 8;
    const int y    = blockIdx.y;

    for (int i = tid; i < 8*DD; i += 256) {
        int r = i >> 8, d = i & 255;
        xs[r][d] = node[(row0 + r)*DD + d];
    }
    if (y == 3 && tid < 96) {
        int r = tid / 12, c = tid % 12;
        if (c < 9) Rs[r][c]   = rot[(row0 + r)*9 + c];
        else       Ts[r][c-9] = trans[(row0 + r)*3 + (c-9)];
    }
    __syncthreads();

    if (y < 3) {
        const float* W = (y == 0) ? Wq : (y == 1) ? Wk : Wv;
        float* G = (y == 0) ? g_qs : (y == 1) ? g_ks : g_vs;
        float acc[8];
        #pragma unroll
        for (int r = 0; r < 8; r++) acc[r] = 0.f;
        const int c = tid;
        #pragma unroll 4
        for (int d = 0; d < DD; d++) {
            float w = W[d*DD + c];
            #pragma unroll
            for (int r = 0; r < 8; r++) acc[r] += xs[r][d]*w;
        }
        const int h = c >> 5, hd = c & 31;
        #pragma unroll
        for (int r = 0; r < 8; r++) {
            int n = row0 + r, b = n >> 9, l = n & 511;
            G[((b*HH + h)*LL + l)*HDH + hd] = acc[r];
        }
        return;
    }

    // ---- point projections ----
    for (int c = tid; c < 288; c += 256) {
        int m = c / 96, cc = c % 96;
        const float* W = (m == 0) ? Wqp : (m == 1) ? Wkp : Wvp;
        float acc[8];
        #pragma unroll
        for (int r = 0; r < 8; r++) acc[r] = 0.f;
        #pragma unroll 4
        for (int d = 0; d < DD; d++) {
            float w = W[d*96 + cc];
            #pragma unroll
            for (int r = 0; r < 8; r++) acc[r] += xs[r][d]*w;
        }
        #pragma unroll
        for (int r = 0; r < 8; r++) lp[m][r][cc] = acc[r];
    }
    __syncthreads();

    for (int i = tid; i < 3*8*96; i += 256) {
        int m = i / 768, rem = i % 768, r = rem / 96, c = rem % 96;
        int base = (c/3)*3, ax = c % 3;
        gp[m][r][c] = Rs[r][ax*3+0]*lp[m][r][base+0]
                    + Rs[r][ax*3+1]*lp[m][r][base+1]
                    + Rs[r][ax*3+2]*lp[m][r][base+2] + Ts[r][ax];
    }
    __syncthreads();

    for (int i = tid; i < 3*8*96; i += 256) {
        int m = i / 768, rem = i % 768, r = rem / 96, c = rem % 96;
        int h = c / 12, cc = c % 12;
        int n = row0 + r, b = n >> 9, l = n & 511;
        int o = ((b*HH + h)*LL + l)*12 + cc;
        float v = gp[m][r][c];
        if (m == 0)      g_qp[o] = v;
        else if (m == 1) g_kp[o] = v;
        else             g_vp[o] = v;
    }
    if (tid < 128) {
        int m = tid >> 6, r = (tid >> 3) & 7, h = tid & 7;
        float s = 0.f;
        #pragma unroll
        for (int c = 0; c < 12; c++) { float v = gp[m][r][h*12 + c]; s += v*v; }
        int n = row0 + r, b = n >> 9, l = n & 511;
        int o = (b*HH + h)*LL + l;
        if (m == 0) g_qn[o] = s; else g_kn[o] = s;
    }
}

// =====================================================================
// K2: fused attention, flash-style online softmax.
// Block = (i-tile of 4, b). 256 threads. j tiles of 32.
// =====================================================================
__global__ __launch_bounds__(256) void k_attn(
    const float* __restrict__ pair,
    const void*  __restrict__ maskp,
    const float* __restrict__ Wpb_g,
    const float* __restrict__ hw,
    const float* __restrict__ rot,
    const float* __restrict__ trans)
{
    __shared__ float pairT[IT*JT*64];    // [i][j][d]
    __shared__ float plog[IT*HH*JT];     // logits -> probabilities
    __shared__ float qs[IT*HH*HDH];
    __shared__ float qp[IT*HH*12];
    __shared__ float qn[IT*HH];
    __shared__ float wpbT[HH*64];        // [h][d]
    __shared__ float s_m[IT*HH], s_l[IT*HH], s_sc[IT*HH];
    __shared__ float wsp[HH];
    __shared__ float RT[IT*12];
    __shared__ float gpts[IT*96];

    const int tid = threadIdx.x;
    const int i0  = blockIdx.x * IT;
    const int b   = blockIdx.y;

    for (int t = tid; t < 512; t += 256)
        wpbT[(t & 7)*64 + (t >> 3)] = Wpb_g[t];
    for (int t = tid; t < IT*256; t += 256) {
        int i = t >> 8, r = t & 255, h = r >> 5, dd = r & 31;
        qs[t] = g_qs[((b*HH + h)*LL + i0 + i)*HDH + dd];
    }
    for (int t = tid; t < IT*96; t += 256) {      // FIXED: was `if (tid < IT*96)`
        int i = t / 96, c = t % 96, h = c / 12, cc = c % 12;
        qp[t] = g_qp[((b*HH + h)*LL + i0 + i)*12 + cc];
    }
    if (tid < IT*HH) {
        int i = tid >> 3, h = tid & 7;
        qn[tid] = g_qn[(b*HH + h)*LL + i0 + i];
        s_m[tid] = -1e30f; s_l[tid] = 0.f;
    }
    if (tid < HH) wsp[tid] = log1pf(expf(hw[tid]));
    if (tid < IT*12) {
        int i = tid / 12, c = tid % 12;
        RT[tid] = (c < 9) ? rot[(b*LL + i0 + i)*9 + c]
                          : trans[(b*LL + i0 + i)*3 + (c - 9)];
    }
    const int mmode = mask_mode(maskp);

    float a_sc[IT], a_pr[2][IT], a_pt[IT];
    #pragma unroll
    for (int i = 0; i < IT; i++) { a_sc[i] = 0.f; a_pr[0][i] = 0.f; a_pr[1][i] = 0.f; a_pt[i] = 0.f; }

    for (int jt = 0; jt < NJT; jt++) {
        const int j0 = jt*JT;
        __syncthreads();   // protect pairT/plog from previous tile consumers

        // ---- stage pair tile: per i, 32j x 64d contiguous = 512 float4 ----
        {
            int i = tid >> 6, q = tid & 63;
            const float4* src = (const float4*)(pair +
                (((size_t)(b*LL + i0 + i))*LL + j0)*64);
            float4* dst = ((float4*)pairT) + i*512;
            #pragma unroll
            for (int u = 0; u < 8; u++) dst[q + u*64] = src[q + u*64];
        }
        __syncthreads();

        // ---- logits: thread = (h, j) ----
        {
            int h = tid >> 5, j = tid & 31;
            const float4* kv = (const float4*)&g_ks[((b*HH + h)*LL + j0 + j)*HDH];
            float4 k4[8];
            #pragma unroll
            for (int u = 0; u < 8; u++) k4[u] = kv[u];
            const float4* kpv = (const float4*)&g_kp[((b*HH + h)*LL + j0 + j)*12];
            float4 kp0 = kpv[0], kp1 = kpv[1], kp2 = kpv[2];
            float kn = g_kn[(b*HH + h)*LL + j0 + j];
            float mpen = mask_at(maskp, mmode, b*LL + j0 + j) ? 0.f : 1e9f;
            float hwc = -0.5f*wsp[h]*POINT_SCALE;

            #pragma unroll
            for (int i = 0; i < IT; i++) {
                const float* q_ = &qs[(i*HH + h)*HDH];
                float s = 0.f;
                #pragma unroll
                for (int u = 0; u < 8; u++) {
                    s += q_[u*4+0]*k4[u].x + q_[u*4+1]*k4[u].y
                       + q_[u*4+2]*k4[u].z + q_[u*4+3]*k4[u].w;
                }
                const float* qpp = &qp[(i*HH + h)*12];
                float pd = qpp[0]*kp0.x + qpp[1]*kp0.y + qpp[2]*kp0.z + qpp[3]*kp0.w
                         + qpp[4]*kp1.x + qpp[5]*kp1.y + qpp[6]*kp1.z + qpp[7]*kp1.w
                         + qpp[8]*kp2.x + qpp[9]*kp2.y + qpp[10]*kp2.z + qpp[11]*kp2.w;
                float bias = 0.f;
                const float* pr = &pairT[(i*JT + j)*64];
                const float* wh = &wpbT[h*64];
                #pragma unroll 8
                for (int dd = 0; dd < 64; dd++) {
                    int d = (dd + j) & 63;          // skew: bank-conflict-free
                    bias += pr[d]*wh[d];
                }
                float dist = qn[i*HH + h] + kn - 2.f*pd;
                plog[(i*HH + h)*JT + j] = s*SCALAR_SCALE + hwc*dist + bias - mpen;
            }
        }
        __syncthreads();

        // ---- online softmax: warp w handles rows 4w..4w+3 of (i,h) ----
        {
            int w = tid >> 5, lane = tid & 31;
            #pragma unroll
            for (int rr = 0; rr < 4; rr++) {
                int r = w*4 + rr;
                float x = plog[r*JT + lane];
                float tm = x;
                #pragma unroll
                for (int o = 16; o; o >>= 1) tm = fmaxf(tm, __shfl_xor_sync(0xffffffffu, tm, o));
                float m_old = s_m[r];
                float m_new = fmaxf(m_old, tm);
                float p = __expf(x - m_new);
                float ts = p;
                #pragma unroll
                for (int o = 16; o; o >>= 1) ts += __shfl_xor_sync(0xffffffffu, ts, o);
                plog[r*JT + lane] = p;
                if (lane == 0) {
                    float sc = __expf(m_old - m_new);
                    s_l[r] = s_l[r]*sc + ts;
                    s_m[r] = m_new;
                    s_sc[r] = sc;
                }
            }
        }
        __syncthreads();

        // ---- accumulate (with rescale) ----
        {   // out_scalar: thread = (h, d32)
            int h = tid >> 5, dd = tid & 31;
            const float* vb = &g_vs[((b*HH + h)*LL + j0)*HDH + dd];
            #pragma unroll
            for (int i = 0; i < IT; i++) a_sc[i] *= s_sc[i*HH + h];
            #pragma unroll 4
            for (int j = 0; j < JT; j++) {
                float v = vb[j*HDH];
                #pragma unroll
                for (int i = 0; i < IT; i++)
                    a_sc[i] += plog[(i*HH + h)*JT + j]*v;
            }
        }
        {   // out_pair: thread = (h-group, d64), 2 h per thread
            int h0 = tid >> 6, d = tid & 63;
            #pragma unroll
            for (int g = 0; g < 2; g++)
                #pragma unroll
                for (int i = 0; i < IT; i++)
                    a_pr[g][i] *= s_sc[i*HH + h0 + g*4];
            #pragma unroll 2
            for (int j = 0; j < JT; j++) {
                #pragma unroll
                for (int i = 0; i < IT; i++) {
                    float pvd = pairT[(i*JT + j)*64 + d];
                    a_pr[0][i] += plog[(i*HH + h0    )*JT + j]*pvd;
                    a_pr[1][i] += plog[(i*HH + h0 + 4)*JT + j]*pvd;
                }
            }
        }
        if (tid < 96) {   // out_points global
            int h = tid / 12, cc = tid % 12;
            const float* vp = &g_vp[((b*HH + h)*LL + j0)*12 + cc];
            #pragma unroll
            for (int i = 0; i < IT; i++) a_pt[i] *= s_sc[i*HH + h];
            #pragma unroll 4
            for (int j = 0; j < JT; j++) {
                float v = vp[j*12];
                #pragma unroll
                for (int i = 0; i < IT; i++)
                    a_pt[i] += plog[(i*HH + h)*JT + j]*v;
            }
        }
    }
    __syncthreads();

    // ---- epilogue: normalize & write feature vector ----
    {
        int h = tid >> 5, dd = tid & 31;
        #pragma unroll
        for (int i = 0; i < IT; i++)
            g_feat[(size_t)(b*LL + i0 + i)*OUTD + h*HDH + dd] = a_sc[i]/s_l[i*HH + h];
    }
    {
        int h0 = tid >> 6, d = tid & 63;
        #pragma unroll
        for (int g = 0; g < 2; g++)
            #pragma unroll
            for (int i = 0; i < IT; i++)
                g_feat[(size_t)(b*LL + i0 + i)*OUTD + 256 + (h0 + g*4)*64 + d]
                    = a_pr[g][i]/s_l[i*HH + h0 + g*4];
    }
    if (tid < 96) {
        int h = tid / 12;
        #pragma unroll
        for (int i = 0; i < IT; i++)
            gpts[i*96 + tid] = a_pt[i]/s_l[i*HH + h];
    }
    __syncthreads();
    if (tid < IT*32) {
        int i = tid >> 5, hp = tid & 31;
        const float* g = &gpts[i*96 + hp*3];
        const float* R = &RT[i*12];
        float d0 = g[0] - R[9], d1 = g[1] - R[10], d2 = g[2] - R[11];
        float l0 = R[0]*d0 + R[3]*d1 + R[6]*d2;
        float l1 = R[1]*d0 + R[4]*d1 + R[7]*d2;
        float l2 = R[2]*d0 + R[5]*d1 + R[8]*d2;
        size_t base = (size_t)(b*LL + i0 + i)*OUTD;
        g_feat[base + 768 + hp*3 + 0] = l0;
        g_feat[base + 768 + hp*3 + 1] = l1;
        g_feat[base + 768 + hp*3 + 2] = l2;
        g_feat[base + 864 + hp] = sqrtf(l0*l0 + l1*l1 + l2*l2);
    }
}

// =====================================================================
// K3: split-K GEMM  g_part[y] = feat[:, y*224:(y+1)*224] @ Wout[y-chunk]
// =====================================================================
__global__ __launch_bounds__(256) void k_gemm_out(const float* __restrict__ Wout)
{
    __shared__ float fs[8][KCH];
    const int tid  = threadIdx.x;
    const int row0 = blockIdx.x * 8;
    const int y    = blockIdx.y;
    const int f0   = y * KCH;

    for (int t = tid; t < 8*(KCH/4); t += 256) {
        int r = t / (KCH/4), q = t % (KCH/4);
        ((float4*)fs[r])[q] =
            *(const float4*)&g_feat[(size_t)(row0 + r)*OUTD + f0 + q*4];
    }
    __syncthreads();

    float acc[8];
    #pragma unroll
    for (int r = 0; r < 8; r++) acc[r] = 0.f;
    const int d = tid;
    for (int f = 0; f < KCH; f += 4) {
        float w0 = Wout[(f0 + f + 0)*DD + d];
        float w1 = Wout[(f0 + f + 1)*DD + d];
        float w2 = Wout[(f0 + f + 2)*DD + d];
        float w3 = Wout[(f0 + f + 3)*DD + d];
        #pragma unroll
        for (int r = 0; r < 8; r++) {
            float4 fv = *(const float4*)&fs[r][f];
            acc[r] += fv.x*w0 + fv.y*w1 + fv.z*w2 + fv.w*w3;
        }
    }
    #pragma unroll
    for (int r = 0; r < 8; r++)
        g_part[(y*NROW + row0 + r)*DD + d] = acc[r];
}

// =====================================================================
// K4: partial reduce + bias + residual + LayerNorm
// =====================================================================
__global__ __launch_bounds__(256) void k_ln(
    const float* __restrict__ node,
    const float* __restrict__ bout,
    const float* __restrict__ gamma,
    const float* __restrict__ beta,
    float* __restrict__ out)
{
    __shared__ float xsm[8][DD];
    __shared__ float s_mu[8], s_inv[8];
    const int tid  = threadIdx.x;
    const int row0 = blockIdx.x * 8;
    const int d = tid;

    const float bo = bout[d];
    #pragma unroll
    for (int r = 0; r < 8; r++) {
        int row = row0 + r;
        float s = node[row*DD + d] + bo;
        #pragma unroll
        for (int y = 0; y < KSPLIT; y++)
            s += g_part[(y*NROW + row)*DD + d];
        xsm[r][d] = s;
    }
    __syncthreads();

    {
        int w = tid >> 5, lane = tid & 31;
        float s = 0.f;
        #pragma unroll
        for (int j = lane; j < DD; j += 32) s += xsm[w][j];
        #pragma unroll
        for (int o = 16; o; o >>= 1) s += __shfl_xor_sync(0xffffffffu, s, o);
        float mu = s * (1.f/DD);
        float v = 0.f;
        #pragma unroll
        for (int j = lane; j < DD; j += 32) { float t = xsm[w][j] - mu; v += t*t; }
        #pragma unroll
        for (int o = 16; o; o >>= 1) v += __shfl_xor_sync(0xffffffffu, v, o);
        if (lane == 0) { s_mu[w] = mu; s_inv[w] = rsqrtf(v*(1.f/DD) + 1e-5f); }
    }
    __syncthreads();

    const float ga = gamma[d], be = beta[d];
    #pragma unroll
    for (int r = 0; r < 8; r++)
        out[(row0 + r)*DD + d] = (xsm[r][d] - s_mu[r])*s_inv[r]*ga + be;
}

// =====================================================================
extern "C" void kernel_launch(void* const* d_in, const int* in_sizes, int n_in,
                              void* d_out, int out_size)
{
    const float* node  = (const float*)d_in[0];
    const float* pair  = (const float*)d_in[1];
    const float* rot   = (const float*)d_in[2];
    const float* trans = (const float*)d_in[3];
    const void*  maskp = (const void*) d_in[4];
    const float* Wq    = (const float*)d_in[5];
    const float* Wk    = (const float*)d_in[6];
    const float* Wv    = (const float*)d_in[7];
    const float* Wqp   = (const float*)d_in[8];
    const float* Wkp   = (const float*)d_in[9];
    const float* Wvp   = (const float*)d_in[10];
    const float* Wpb   = (const float*)d_in[11];
    const float* hw    = (const float*)d_in[12];
    const float* Wout  = (const float*)d_in[13];
    const float* bout  = (const float*)d_in[14];
    const float* gamma = (const float*)d_in[15];
    const float* beta  = (const float*)d_in[16];
    float* out = (float*)d_out;

    k_proj<<<dim3(NROW/8, 4), 256>>>(node, rot, trans, Wq, Wk, Wv, Wqp, Wkp, Wvp);
    k_attn<<<dim3(LL/IT, BB), 256>>>(pair, maskp, Wpb, hw, rot, trans);
    k_gemm_out<<<dim3(NROW/8, KSPLIT), 256>>>(Wout);
    k_ln<<<NROW/8, 256>>>(node, bout, gamma, beta, out);
}